// round 15
// baseline (speedup 1.0000x reference)
#include <cuda_runtime.h>
#include <cuda_fp16.h>
#include <cstdint>

#define NN 25000
#define NE 400000

#if defined(__CUDA_ARCH_FEAT_SM103_ALL) || defined(__CUDA_ARCH_FEAT_SM101_ALL) || defined(__CUDA_ARCH_FEAT_SM100_ALL)
#define HAS_TCGEN05 1
#else
#define HAS_TCGEN05 0
#endif

typedef unsigned long long u64;

// ---------------- scratch ----------------
__device__ __align__(16) float g_Ai[NN * 8];
__device__ float g_cnt[NN];
// prepped gw4: 8 chunks x 8192 words (tf32 SW128 blocked) + bias 4096 words
__device__ __align__(16) uint32_t g_W2[8 * 8192 + 4096];
// prepped gw2/gw3: 2 x 4096 words (tf32 SW128 blocked, 8 atom-rows x 2 atom-cols)
__device__ __align__(16) uint32_t g_W23[8192];

__device__ __forceinline__ float silu_f(float v) {
    return v * __fdividef(1.0f, 1.0f + __expf(-v));
}

// ---- packed f32x2 (fallback path) ----
__device__ __forceinline__ u64 f2fma(u64 a, u64 b, u64 c) {
    u64 d; asm("fma.rn.f32x2 %0,%1,%2,%3;" : "=l"(d) : "l"(a), "l"(b), "l"(c)); return d;
}
__device__ __forceinline__ u64 f2mul(u64 a, u64 b) {
    u64 d; asm("mul.rn.f32x2 %0,%1,%2;" : "=l"(d) : "l"(a), "l"(b)); return d;
}
__device__ __forceinline__ u64 f2add(u64 a, u64 b) {
    u64 d; asm("add.rn.f32x2 %0,%1,%2;" : "=l"(d) : "l"(a), "l"(b)); return d;
}
__device__ __forceinline__ u64 fpack(float lo, float hi) {
    u64 d; asm("mov.b64 %0,{%1,%2};" : "=l"(d) : "f"(lo), "f"(hi)); return d;
}
__device__ __forceinline__ float2 funpack(u64 v) {
    float lo, hi; asm("mov.b64 {%0,%1},%2;" : "=f"(lo), "=f"(hi) : "l"(v));
    return make_float2(lo, hi);
}

// ---- scalar 64->64 layer (fallback path only) ----
__device__ __forceinline__ void layer64p(const float* __restrict__ Wt,
                                         const float* __restrict__ Bv,
                                         const u64 (&in)[32], u64 (&outp)[32])
{
    #pragma unroll
    for (int k = 0; k < 64; k += 2) {
        float o[2];
        #pragma unroll
        for (int kk = 0; kk < 2; kk++) {
            const u64* wr = (const u64*)(Wt + (k + kk) * 64);
            ulonglong2 w01 = *(const ulonglong2*)(wr);
            ulonglong2 w23 = *(const ulonglong2*)(wr + 2);
            u64 a0 = f2mul(w01.x, in[0]);
            u64 a1 = f2mul(w01.y, in[1]);
            u64 a2 = f2mul(w23.x, in[2]);
            u64 a3 = f2mul(w23.y, in[3]);
            #pragma unroll
            for (int i = 4; i < 32; i += 4) {
                ulonglong2 v01 = *(const ulonglong2*)(wr + i);
                ulonglong2 v23 = *(const ulonglong2*)(wr + i + 2);
                a0 = f2fma(v01.x, in[i + 0], a0);
                a1 = f2fma(v01.y, in[i + 1], a1);
                a2 = f2fma(v23.x, in[i + 2], a2);
                a3 = f2fma(v23.y, in[i + 3], a3);
            }
            u64 s = f2add(f2add(a0, a1), f2add(a2, a3));
            float2 sv = funpack(s);
            o[kk] = silu_f(sv.x + sv.y + Bv[k + kk]);
        }
        outp[k >> 1] = fpack(o[0], o[1]);
    }
}

#if HAS_TCGEN05
// ---------------- tcgen05 plumbing ----------------
__device__ __forceinline__ uint32_t smem_u32(const void* p) {
    uint32_t a;
    asm("{ .reg .u64 t; cvta.to.shared.u64 t, %1; cvt.u32.u64 %0, t; }" : "=r"(a) : "l"(p));
    return a;
}
__device__ __forceinline__ uint32_t elect1() {
    uint32_t p;
    asm volatile("{\n\t.reg .pred p;\n\telect.sync _|p, 0xFFFFFFFF;\n\tselp.b32 %0,1,0,p;\n\t}" : "=r"(p));
    return p;
}
__device__ __forceinline__ uint32_t to_tf32(float f) {
    uint32_t r; asm("cvt.rna.tf32.f32 %0,%1;" : "=r"(r) : "f"(f)); return r;
}

#define TCGEN05_ALLOC(saddr, ncols) \
    asm volatile("tcgen05.alloc.cta_group::1.sync.aligned.shared::cta.b32 [%0], %1;" \
                 :: "r"((uint32_t)(saddr)), "r"((uint32_t)(ncols)) : "memory")
#define TCGEN05_RELINQ() \
    asm volatile("tcgen05.relinquish_alloc_permit.cta_group::1.sync.aligned;")
#define TCGEN05_DEALLOC(tmem, ncols) \
    asm volatile("tcgen05.dealloc.cta_group::1.sync.aligned.b32 %0, %1;" :: "r"(tmem), "r"((uint32_t)(ncols)))
#define TCGEN05_COMMIT(mbar) \
    asm volatile("tcgen05.commit.cta_group::1.mbarrier::arrive::one.shared::cluster.b64 [%0];" \
                 :: "r"((uint32_t)(mbar)) : "memory")
#define TCGEN05_WAIT_ST()  asm volatile("tcgen05.wait::st.sync.aligned;" ::: "memory")
#define TCGEN05_WAIT_LD()  asm volatile("tcgen05.wait::ld.sync.aligned;" ::: "memory")
#define TCGEN05_FENCE_BEFORE() asm volatile("tcgen05.fence::before_thread_sync;" ::: "memory")
#define TCGEN05_FENCE_AFTER()  asm volatile("tcgen05.fence::after_thread_sync;" ::: "memory")
#define FENCE_PROXY() asm volatile("fence.proxy.async.shared::cta;" ::: "memory")
#define MBARRIER_INIT(mbar, cnt) \
    asm volatile("mbarrier.init.shared.b64 [%0], %1;" :: "r"((uint32_t)(mbar)), "r"((uint32_t)(cnt)) : "memory")
#define MBARRIER_EXPECT_TX(mbar, bytes) \
    asm volatile("mbarrier.arrive.expect_tx.shared.b64 _, [%0], %1;" \
                 :: "r"((uint32_t)(mbar)), "r"((uint32_t)(bytes)) : "memory")
#define BULK_G2S(dst, src, bytes, mbar) \
    asm volatile("cp.async.bulk.shared::cluster.global.mbarrier::complete_tx::bytes [%0], [%1], %2, [%3];" \
                 :: "r"((uint32_t)(dst)), "l"(src), "r"((uint32_t)(bytes)), "r"((uint32_t)(mbar)) : "memory")
#define MBARRIER_WAIT0(mbar_a) do { \
    uint32_t _m = (uint32_t)(mbar_a); uint32_t _d; \
    asm volatile("{\n\t.reg .pred p;\n\tmbarrier.try_wait.parity.acquire.cta.shared::cta.b64 p, [%1], 0;\n\tselp.b32 %0,1,0,p;\n\t}" \
        : "=r"(_d) : "r"(_m) : "memory"); \
    if (!_d) { \
        asm volatile("{\n\t.reg .pred P1;\n\tWL_%=:\n\tmbarrier.try_wait.parity.acquire.cta.shared::cta.b64 P1, [%0], 0, 0x989680;\n\t@P1 bra.uni WD_%=;\n\tbra.uni WL_%=;\n\tWD_%=:\n\t}" \
            :: "r"(_m) : "memory"); \
    } \
} while (0)

#define TCGEN05_LD_X32(r, addr) \
    asm volatile("tcgen05.ld.sync.aligned.32x32b.x32.b32 " \
        "{%0,%1,%2,%3,%4,%5,%6,%7,%8,%9,%10,%11,%12,%13,%14,%15," \
        "%16,%17,%18,%19,%20,%21,%22,%23,%24,%25,%26,%27,%28,%29,%30,%31}, [%32];" \
        : "=r"((r)[0]),"=r"((r)[1]),"=r"((r)[2]),"=r"((r)[3]),"=r"((r)[4]),"=r"((r)[5]),"=r"((r)[6]),"=r"((r)[7]), \
          "=r"((r)[8]),"=r"((r)[9]),"=r"((r)[10]),"=r"((r)[11]),"=r"((r)[12]),"=r"((r)[13]),"=r"((r)[14]),"=r"((r)[15]), \
          "=r"((r)[16]),"=r"((r)[17]),"=r"((r)[18]),"=r"((r)[19]),"=r"((r)[20]),"=r"((r)[21]),"=r"((r)[22]),"=r"((r)[23]), \
          "=r"((r)[24]),"=r"((r)[25]),"=r"((r)[26]),"=r"((r)[27]),"=r"((r)[28]),"=r"((r)[29]),"=r"((r)[30]),"=r"((r)[31]) \
        : "r"(addr))

#define TCGEN05_ST_X32(addr, r) \
    asm volatile("tcgen05.st.sync.aligned.32x32b.x32.b32 [%0], " \
        "{%1,%2,%3,%4,%5,%6,%7,%8,%9,%10,%11,%12,%13,%14,%15,%16," \
        "%17,%18,%19,%20,%21,%22,%23,%24,%25,%26,%27,%28,%29,%30,%31,%32};" \
        :: "r"(addr), \
           "r"((r)[0]),"r"((r)[1]),"r"((r)[2]),"r"((r)[3]),"r"((r)[4]),"r"((r)[5]),"r"((r)[6]),"r"((r)[7]), \
           "r"((r)[8]),"r"((r)[9]),"r"((r)[10]),"r"((r)[11]),"r"((r)[12]),"r"((r)[13]),"r"((r)[14]),"r"((r)[15]), \
           "r"((r)[16]),"r"((r)[17]),"r"((r)[18]),"r"((r)[19]),"r"((r)[20]),"r"((r)[21]),"r"((r)[22]),"r"((r)[23]), \
           "r"((r)[24]),"r"((r)[25]),"r"((r)[26]),"r"((r)[27]),"r"((r)[28]),"r"((r)[29]),"r"((r)[30]),"r"((r)[31]) \
        : "memory")

static constexpr uint32_t IDESC_N64  = (1u << 4) | (2u << 7) | (2u << 10) | (8u << 17)  | (8u << 24);
static constexpr uint32_t IDESC_N128 = (1u << 4) | (2u << 7) | (2u << 10) | (16u << 17) | (8u << 24);
static constexpr uint64_t DESC_BASE =
    (uint64_t(2) << 61) | (uint64_t(1) << 46) | (uint64_t(64) << 32) | (uint64_t(1) << 16);
__device__ __forceinline__ uint64_t mkdesc(uint32_t saddr) {
    return DESC_BASE | ((uint64_t)(saddr >> 4) & 0x3FFF);
}
__device__ __forceinline__ void mma_tf32(uint32_t d, uint32_t a, uint64_t bd, uint32_t idesc, bool acc) {
    uint32_t en = acc ? 1u : 0u;
    asm volatile(
        "{\n\t.reg .pred p;\n\tsetp.ne.u32 p, %4, 0;\n\t"
        "tcgen05.mma.cta_group::1.kind::tf32 [%0], [%1], %2, %3, {%5,%5,%5,%5}, p;\n\t}"
        :: "r"(d), "r"(a), "l"(bd), "r"(idesc), "r"(en), "r"(0u) : "memory");
}
__device__ __forceinline__ int w2_scol(int i, int n) {
    return (n < 64) ? (i * 64 + n)
         : (n < 96) ? (512 + i * 32 + (n - 64))
                    : (768 + i * 32 + (n - 96));
}
// chunk K-step desc offsets (16 atom-rows): atom-col 1 at 16KB
__device__ __forceinline__ uint64_t koff(int s)  { return (uint64_t)((s & 3) * 2 + (s >> 2) * 1024); }
// layer K-step desc offsets (8 atom-rows): atom-col 1 at 8KB
__device__ __forceinline__ uint64_t koffL(int s) { return (uint64_t)((s & 3) * 2 + (s >> 2) * 512); }
#endif // HAS_TCGEN05

// ---------------- fallback L4 helper ----------------
template<int MUL, int GB>
__device__ __forceinline__ void chunk_accum_f(const float* __restrict__ sChunk,
                                              const float* __restrict__ sBias,
                                              const float* __restrict__ sAs,
                                              const float* __restrict__ sAd,
                                              int tid, int pair_base,
                                              const u64 (&h3)[32], u64 (&g)[16])
{
    const int NP = 128 / MUL;
    #pragma unroll 1
    for (int p = 0; p < NP; p++) {
        int ij = pair_base + p;
        float pij = sAs[(ij >> 3) * 256 + tid] * sAd[(ij & 7) * 256 + tid];
        u64 pijp = fpack(pij, pij);
        const float* colb = sChunk + p * MUL * 68;
        #pragma unroll
        for (int u = 0; u < MUL; u++) {
            const u64* col = (const u64*)(colb + u * 68);
            ulonglong2 w01 = *(const ulonglong2*)(col);
            ulonglong2 w23 = *(const ulonglong2*)(col + 2);
            u64 a0 = f2fma(w01.x, h3[0], fpack(sBias[p * MUL + u], 0.0f));
            u64 a1 = f2mul(w01.y, h3[1]);
            u64 a2 = f2mul(w23.x, h3[2]);
            u64 a3 = f2mul(w23.y, h3[3]);
            #pragma unroll
            for (int i = 4; i < 32; i += 4) {
                ulonglong2 v01 = *(const ulonglong2*)(col + i);
                ulonglong2 v23 = *(const ulonglong2*)(col + i + 2);
                a0 = f2fma(v01.x, h3[i + 0], a0);
                a1 = f2fma(v01.y, h3[i + 1], a1);
                a2 = f2fma(v23.x, h3[i + 2], a2);
                a3 = f2fma(v23.y, h3[i + 3], a3);
            }
            u64 s = f2add(f2add(a0, a1), f2add(a2, a3));
            g[GB + u] = f2fma(pijp, s, g[GB + u]);
        }
    }
}

// ---------------- zero ----------------
__global__ void zero_kernel(float* __restrict__ out) {
    int i = blockIdx.x * 256 + threadIdx.x;
    if (i < NN * 40) out[i] = 0.0f;
    if (i < NN) g_cnt[i] = 0.0f;
}

// ---------------- prep: gw4 -> g_W2, gw2/gw3 -> g_W23 (tf32 SW128 blocked) ----------------
__global__ void prep_w2(const float* __restrict__ gw4, const float* __restrict__ gb4,
                        const float* __restrict__ gw2, const float* __restrict__ gw3) {
#if HAS_TCGEN05
    int idx = blockIdx.x * 256 + threadIdx.x;
    if (idx < 65536) {
        int c = idx >> 13, r = idx & 8191;
        int pk = r >> 7, n = r & 127;
        int p = c * 64 + pk;
        int k = p >> 3, i = p & 7;
        uint32_t off = (uint32_t)(((n >> 3) + (pk >> 5) * 16) * 1024 + (n & 7) * 128 + (pk & 31) * 4);
        off ^= (off >> 3) & 0x70;
        g_W2[c * 8192 + (off >> 2)] = to_tf32(gw4[k * 1024 + w2_scol(i, n)]);
    } else if (idx < 65536 + 1024) {
        int r = idx - 65536;
        int pk = r >> 7, n = r & 127;
        uint32_t off = (uint32_t)((n >> 3) * 1024 + (n & 7) * 128 + pk * 4);
        off ^= (off >> 3) & 0x70;
        g_W2[65536 + (off >> 2)] = to_tf32(gb4[w2_scol(pk, n)]);
    } else if (idx < 65536 + 1024 + 8192) {
        int r = idx - 66560;
        int layer = r >> 12, rr = r & 4095;
        int k = rr >> 6, n = rr & 63;
        const float* W = layer ? gw3 : gw2;
        uint32_t off = (uint32_t)(((n >> 3) + (k >> 5) * 8) * 1024 + (n & 7) * 128 + (k & 31) * 4);
        off ^= (off >> 3) & 0x70;
        g_W23[layer * 4096 + (off >> 2)] = to_tf32(W[k * 64 + n]);
    }
#endif
}

// ---------------- atom MLP 16->64->32->8 ----------------
__global__ void atom_kernel(const float* __restrict__ atom_table,
                            const float* __restrict__ fw1, const float* __restrict__ fb1,
                            const float* __restrict__ fw2, const float* __restrict__ fb2,
                            const float* __restrict__ fw3, const float* __restrict__ fb3,
                            const int* __restrict__ A)
{
    __shared__ float s[1024 + 64 + 2048 + 32 + 256 + 8];
    float* sW1 = s;             float* sB1 = sW1 + 1024;
    float* sW2 = sB1 + 64;      float* sB2 = sW2 + 2048;
    float* sW3 = sB2 + 32;      float* sB3 = sW3 + 256;
    int tid = threadIdx.x;
    for (int i = tid; i < 1024; i += 256) sW1[i] = fw1[i];
    for (int i = tid; i < 2048; i += 256) sW2[i] = fw2[i];
    for (int i = tid; i < 256; i += 256) sW3[i] = fw3[i];
    if (tid < 64) sB1[tid] = fb1[tid];
    if (tid < 32) sB2[tid] = fb2[tid];
    if (tid < 8)  sB3[tid] = fb3[tid];
    __syncthreads();

    int n = blockIdx.x * 256 + tid;
    if (n >= NN) return;
    float e[16];
    const float* at = atom_table + A[n] * 16;
    #pragma unroll
    for (int i = 0; i < 16; i++) e[i] = at[i];
    float h1[64];
    #pragma unroll
    for (int k = 0; k < 64; k++) {
        float a = sB1[k];
        #pragma unroll
        for (int i = 0; i < 16; i++) a = fmaf(e[i], sW1[i * 64 + k], a);
        h1[k] = silu_f(a);
    }
    float h2[32];
    #pragma unroll
    for (int k = 0; k < 32; k++) {
        float a = sB2[k];
        #pragma unroll
        for (int i = 0; i < 64; i++) a = fmaf(h1[i], sW2[i * 32 + k], a);
        h2[k] = silu_f(a);
    }
    #pragma unroll
    for (int k = 0; k < 8; k++) {
        float a = sB3[k];
        #pragma unroll
        for (int i = 0; i < 32; i++) a = fmaf(h2[i], sW3[i * 8 + k], a);
        g_Ai[n * 8 + k] = a;
    }
}

// ================================================================
// TENSOR kernel: 256 edges/CTA (two M=128 tiles sharing each weight
// load). All L2/L3/L4 on tcgen05; bias seeds D; pipelined L4.
// 256 threads, TMEM 512 cols, 1 CTA/SM.
// ================================================================
__global__ void __launch_bounds__(256, 1) edge_tensor(
    const float* __restrict__ pos, const float* __restrict__ shifts,
    const float* __restrict__ cell,
    const float* __restrict__ gw1, const float* __restrict__ gb1,
    const float* __restrict__ gb2, const float* __restrict__ gb3,
    const int* __restrict__ batch,
    const int* __restrict__ esrc, const int* __restrict__ edst,
    float* __restrict__ out)
{
#if HAS_TCGEN05
    extern __shared__ float smraw[];
    char* ab = (char*)(((uintptr_t)(char*)smraw + 1023) & ~(uintptr_t)1023);
    float* smf  = (float*)ab;
    // words: buf0 [0,8192) buf1 [8192,16384) biasb [16384,20480) sH3h [20480,28672)
    __half* sH3h = (__half*)(smf + 20480);   // [k][tid], 64x256 fp16 (32KB)
    float* sG1T = smf + 28672;   // 512
    float* sB1  = smf + 29184;   // 64
    float* sB2  = smf + 29248;   // 64
    float* sB3  = smf + 29312;   // 64
    volatile uint32_t* sTm = (volatile uint32_t*)(smf + 29376);
    uint32_t mbar0 = smem_u32((const void*)(smf + 29378));  // 21 x 8B
    #define MBAR(i) (mbar0 + 8u * (uint32_t)(i))
    // 0..7 copy chunk c; 8 copy bias; 9..16 mma chunk c (both tiles); 17 mma bias; 18 mma L2; 19 mma L3; 20 copy W23

    int tid = threadIdx.x;
    int wid = tid >> 5;
    uint32_t tile = (uint32_t)(tid >> 7);            // 0 or 1
    uint32_t woff = ((uint32_t)wid & 3u) << 21;      // lane group within tile
    uint32_t smem_base32 = smem_u32(ab);

    if (wid == 0) {
        TCGEN05_ALLOC(smem_u32((const void*)sTm), 512);
        TCGEN05_RELINQ();
    }
    if (tid == 0) {
        #pragma unroll
        for (int i = 0; i < 21; i++) MBARRIER_INIT(MBAR(i), 1);
        // prologue: W23 -> buf0, chunk0 -> buf1, bias -> biasb
        MBARRIER_EXPECT_TX(MBAR(20), 32768);
        BULK_G2S(smem_base32, (const void*)(g_W23), 32768, MBAR(20));
        MBARRIER_EXPECT_TX(MBAR(0), 32768);
        BULK_G2S(smem_base32 + 32768u, (const void*)(g_W2), 32768, MBAR(0));
        MBARRIER_EXPECT_TX(MBAR(8), 16384);
        BULK_G2S(smem_base32 + 65536u, (const void*)(g_W2 + 65536), 16384, MBAR(8));
    }

    // stage small scalar weights
    for (int i = tid; i < 512; i += 256) { int ii = i >> 6, k = i & 63; sG1T[k * 8 + ii] = gw1[i]; }
    if (tid < 64) { sB1[tid] = gb1[tid]; sB2[tid] = gb2[tid]; sB3[tid] = gb3[tid]; }

    // ---- per-edge geometry (grid 1563; last CTA has 128-edge tail) ----
    int e = blockIdx.x * 256 + tid;
    bool valid = e < NE;
    int ee = valid ? e : (NE - 1);
    int src = esrc[ee], dst = edst[ee];

    float s0 = shifts[ee * 3 + 0], s1 = shifts[ee * 3 + 1], s2 = shifts[ee * 3 + 2];
    const float* cb = cell + batch[src] * 9;
    float vx = pos[dst * 3 + 0] - pos[src * 3 + 0] + s0 * cb[0] + s1 * cb[3] + s2 * cb[6];
    float vy = pos[dst * 3 + 1] - pos[src * 3 + 1] + s0 * cb[1] + s1 * cb[4] + s2 * cb[7];
    float vz = pos[dst * 3 + 2] - pos[src * 3 + 2] + s0 * cb[2] + s1 * cb[5] + s2 * cb[8];
    float r  = sqrtf(vx * vx + vy * vy + vz * vz + 1e-12f);
    float ir = __fdividef(1.0f, r);
    float ux = vx * ir, uy = vy * ir, uz = vz * ir;

    float sh[9];
    sh[0] = 1.0f;
    sh[1] = 1.7320508075688772f * ux;
    sh[2] = 1.7320508075688772f * uy;
    sh[3] = 1.7320508075688772f * uz;
    sh[4] = 3.872983346207417f * ux * uy;
    sh[5] = 3.872983346207417f * uy * uz;
    sh[6] = 1.118033988749895f * (2.0f * uz * uz - ux * ux - uy * uy);
    sh[7] = 3.872983346207417f * ux * uz;
    sh[8] = 1.9364916731037085f * (ux * ux - uy * uy);

    float xr = fminf(r * 0.2f, 1.0f);
    float mk = (r <= 5.0f) ? 2.8284271247461903f : 0.0f;
    float emb[8];
    #pragma unroll
    for (int j = 0; j < 8; j++) {
        float t = (xr - (float)j * (1.0f / 7.0f)) * 7.0f;
        emb[j] = __expf(-0.5f * t * t) * mk;
    }

    float As[8], Ad[8];
    {
        float4 a0 = *(const float4*)(g_Ai + src * 8);
        float4 a1 = *(const float4*)(g_Ai + src * 8 + 4);
        float4 b0 = *(const float4*)(g_Ai + dst * 8);
        float4 b1 = *(const float4*)(g_Ai + dst * 8 + 4);
        As[0]=a0.x; As[1]=a0.y; As[2]=a0.z; As[3]=a0.w; As[4]=a1.x; As[5]=a1.y; As[6]=a1.z; As[7]=a1.w;
        Ad[0]=b0.x; Ad[1]=b0.y; Ad[2]=b0.z; Ad[3]=b0.w; Ad[4]=b1.x; Ad[5]=b1.y; Ad[6]=b1.z; Ad[7]=b1.w;
    }

    __syncthreads();        // alloc + staging visible
    uint32_t tb = *sTm;     // TMEM: A tile t = t*128 (two 64-col halves); D tile t = 256 + t*128
    uint32_t At = tb + tile * 128u;
    uint32_t Dt = tb + 256u + tile * 128u;

    // ---- L1 scalar (8->64) -> STTM A_t[0..63] ----
    #pragma unroll
    for (int b = 0; b < 2; b++) {
        uint32_t rr[32];
        #pragma unroll
        for (int kk = 0; kk < 32; kk++) {
            int k = b * 32 + kk;
            float a = sB1[k];
            #pragma unroll
            for (int i = 0; i < 8; i++) a = fmaf(emb[i], sG1T[k * 8 + i], a);
            rr[kk] = to_tf32(silu_f(a));
        }
        TCGEN05_ST_X32(At + b * 32 + woff, rr);
    }
    TCGEN05_WAIT_ST();
    TCGEN05_FENCE_BEFORE();
    __syncthreads();

    // ---- L2 MMA (both tiles): D_t[0..63] = h1_t @ gw2t (buf0 lo) ----
    if (wid == 0) {
        TCGEN05_FENCE_AFTER();
        MBARRIER_WAIT0(MBAR(20));
        if (elect1()) {
            uint64_t bd = mkdesc(smem_base32);
            #pragma unroll
            for (int t = 0; t < 2; t++)
                #pragma unroll
                for (int s = 0; s < 8; s++)
                    mma_tf32(tb + 256u + (uint32_t)t * 128u,
                             tb + (uint32_t)t * 128u + (uint32_t)s * 8u,
                             bd + koffL(s), IDESC_N64, s > 0);
            TCGEN05_COMMIT(MBAR(18));
        }
    }
    MBARRIER_WAIT0(MBAR(18));
    TCGEN05_FENCE_AFTER();

    // act L2: h2 -> A_t[64..127]
    #pragma unroll
    for (int b = 0; b < 2; b++) {
        uint32_t rr[32];
        TCGEN05_LD_X32(rr, Dt + b * 32 + woff);
        TCGEN05_WAIT_LD();
        #pragma unroll
        for (int i = 0; i < 32; i++) rr[i] = to_tf32(silu_f(__uint_as_float(rr[i]) + sB2[b * 32 + i]));
        TCGEN05_ST_X32(At + 64u + b * 32 + woff, rr);
    }
    TCGEN05_WAIT_ST();
    TCGEN05_FENCE_BEFORE();
    __syncthreads();

    // ---- L3 MMA (both tiles): D_t[0..63] = h2_t @ gw3t (buf0 hi) ----
    if (wid == 0) {
        TCGEN05_FENCE_AFTER();
        if (elect1()) {
            uint64_t bd = mkdesc(smem_base32 + 16384u);
            #pragma unroll
            for (int t = 0; t < 2; t++)
                #pragma unroll
                for (int s = 0; s < 8; s++)
                    mma_tf32(tb + 256u + (uint32_t)t * 128u,
                             tb + (uint32_t)t * 128u + 64u + (uint32_t)s * 8u,
                             bd + koffL(s), IDESC_N64, s > 0);
            TCGEN05_COMMIT(MBAR(19));
        }
    }
    MBARRIER_WAIT0(MBAR(19));
    TCGEN05_FENCE_AFTER();
    if (tid == 0) {   // buf0 consumed -> DMA chunk1 over it
        MBARRIER_EXPECT_TX(MBAR(1), 32768);
        BULK_G2S(smem_base32, (const void*)(g_W2 + 8192), 32768, MBAR(1));
    }

    // act L3: h3 = silu(D + gb3) -> sH3h (fp16)
    #pragma unroll
    for (int b = 0; b < 2; b++) {
        uint32_t rr[32];
        TCGEN05_LD_X32(rr, Dt + b * 32 + woff);
        TCGEN05_WAIT_LD();
        #pragma unroll
        for (int i = 0; i < 32; i++)
            sH3h[(b * 32 + i) * 256 + tid] = __float2half_rn(silu_f(__uint_as_float(rr[i]) + sB3[b * 32 + i]));
    }

    // ---- bias MMA seeds D (acc=false), both tiles ----
    {
        uint32_t rr[32];
        #pragma unroll
        for (int c = 0; c < 32; c++) rr[c] = (c < 8) ? to_tf32(As[c]) : 0u;
        TCGEN05_ST_X32(At + woff, rr);
        TCGEN05_WAIT_ST();
        TCGEN05_FENCE_BEFORE();
        __syncthreads();
        if (wid == 0) {
            TCGEN05_FENCE_AFTER();
            MBARRIER_WAIT0(MBAR(8));
            if (elect1()) {
                uint64_t bd = mkdesc(smem_base32 + 65536u);
                #pragma unroll
                for (int t = 0; t < 2; t++)
                    mma_tf32(tb + 256u + (uint32_t)t * 128u, tb + (uint32_t)t * 128u, bd, IDESC_N128, false);
                TCGEN05_COMMIT(MBAR(17));
            }
        }
        MBARRIER_WAIT0(MBAR(17));   // A[0..63] free for part0
        TCGEN05_FENCE_AFTER();
    }

    // ---- L4: 8 pipelined parts; A-half ping-pong; D accumulates; chunks shared by both tiles ----
    #pragma unroll 1
    for (int c = 0; c < 8; c++) {
        if (c >= 2) {
            MBARRIER_WAIT0(MBAR(9 + c - 2));      // frees A-half(c&1) and chunk-c's buffer
            TCGEN05_FENCE_AFTER();
            if (tid == 0) {
                MBARRIER_EXPECT_TX(MBAR(c), 32768);
                BULK_G2S(smem_base32 + ((c & 1) ? 0u : 32768u),
                         (const void*)(g_W2 + c * 8192), 32768, MBAR(c));
            }
        }
        uint32_t abase = At + (uint32_t)(c & 1) * 64u;
        #pragma unroll
        for (int b = 0; b < 2; b++) {
            float hv0 = __half2float(sH3h[(8 * c + 4 * b + 0) * 256 + tid]);
            float hv1 = __half2float(sH3h[(8 * c + 4 * b + 1) * 256 + tid]);
            float hv2 = __half2float(sH3h[(8 * c + 4 * b + 2) * 256 + tid]);
            float hv3 = __half2float(sH3h[(8 * c + 4 * b + 3) * 256 + tid]);
            uint32_t rr[32];
            #pragma unroll
            for (int j = 0; j < 8; j++) {
                rr[j]      = to_tf32(hv0 * As[j]);
                rr[8 + j]  = to_tf32(hv1 * As[j]);
                rr[16 + j] = to_tf32(hv2 * As[j]);
                rr[24 + j] = to_tf32(hv3 * As[j]);
            }
            TCGEN05_ST_X32(abase + 32u * b + woff, rr);
        }
        TCGEN05_WAIT_ST();
        TCGEN05_FENCE_BEFORE();
        __syncthreads();

        if (wid == 0) {
            TCGEN05_FENCE_AFTER();
            MBARRIER_WAIT0(MBAR(c));              // DMA complete
            if (elect1()) {
                uint64_t bd = mkdesc(smem_base32 + ((c & 1) ? 0u : 32768u));
                #pragma unroll
                for (int t = 0; t < 2; t++)
                    #pragma unroll
                    for (int s = 0; s < 8; s++)
                        mma_tf32(tb + 256u + (uint32_t)t * 128u,
                                 tb + (uint32_t)t * 128u + (uint32_t)(c & 1) * 64u + (uint32_t)s * 8u,
                                 bd + koff(s), IDESC_N128, true);
                TCGEN05_COMMIT(MBAR(9 + c));
            }
        }
    }

    // ---- final waits + single readback + fold ----
    MBARRIER_WAIT0(MBAR(9 + 6));
    MBARRIER_WAIT0(MBAR(9 + 7));
    TCGEN05_FENCE_AFTER();

    float g[16];
    #pragma unroll
    for (int i = 0; i < 16; i++) g[i] = 0.0f;
    #pragma unroll
    for (int q = 0; q < 4; q++) {
        uint32_t rr[32];
        TCGEN05_LD_X32(rr, Dt + 32u * q + woff);
        TCGEN05_WAIT_LD();
        if (q < 2) {
            #pragma unroll
            for (int c = 0; c < 32; c++)
                g[c & 7] = fmaf(Ad[4 * q + (c >> 3)], __uint_as_float(rr[c]), g[c & 7]);
        } else if (q == 2) {
            #pragma unroll
            for (int c = 0; c < 32; c++)
                g[8 + (c & 3)] = fmaf(Ad[c >> 2], __uint_as_float(rr[c]), g[8 + (c & 3)]);
        } else {
            #pragma unroll
            for (int c = 0; c < 32; c++)
                g[12 + (c & 3)] = fmaf(Ad[c >> 2], __uint_as_float(rr[c]), g[12 + (c & 3)]);
        }
    }

    // ---- scatter ----
    if (valid) {
        float* o = out + dst * 40;
        const float alpha = 0.125f;
        #pragma unroll
        for (int u = 0; u < 8; u++) atomicAdd(o + u, alpha * g[u]);
        #pragma unroll
        for (int u = 0; u < 4; u++)
            #pragma unroll
            for (int m = 0; m < 3; m++)
                atomicAdd(o + 8 + u * 3 + m, alpha * g[8 + u] * sh[1 + m]);
        #pragma unroll
        for (int u = 0; u < 4; u++)
            #pragma unroll
            for (int m = 0; m < 5; m++)
                atomicAdd(o + 20 + u * 5 + m, alpha * g[12 + u] * sh[4 + m]);
        atomicAdd(&g_cnt[dst], 1.0f);
    }

    __syncthreads();
    if (wid == 0) TCGEN05_DEALLOC(tb, 512);
    #undef MBAR
#endif
}

// ================================================================
// FALLBACK kernel (R3 body). No-op on sm_103a builds.
// ================================================================
__global__ void __launch_bounds__(256) edge_fallback(
    const float* __restrict__ pos, const float* __restrict__ shifts,
    const float* __restrict__ cell,
    const float* __restrict__ gw1, const float* __restrict__ gb1,
    const float* __restrict__ gw2, const float* __restrict__ gb2,
    const float* __restrict__ gw3, const float* __restrict__ gb3,
    const float* __restrict__ gw4, const float* __restrict__ gb4,
    const int* __restrict__ batch,
    const int* __restrict__ esrc, const int* __restrict__ edst,
    float* __restrict__ out)
{
#if !HAS_TCGEN05
    extern __shared__ float sm[];
    float* sG1T  = sm;
    float* sB1   = sG1T + 512;
    float* sG2T  = sB1 + 64;
    float* sB2   = sG2T + 4096;
    float* sG3T  = sB2 + 64;
    float* sB3   = sG3T + 4096;
    float* sAs   = sB3 + 64;
    float* sAd   = sAs + 8 * 256;
    float* sBias = sAd + 8 * 256;
    float* sChunk = sBias + 128;

    int tid = threadIdx.x;
    for (int idx = tid; idx < 512; idx += 256) {
        int i = idx >> 6, k = idx & 63;
        sG1T[k * 8 + i] = gw1[idx];
    }
    for (int idx = tid; idx < 4096; idx += 256) {
        int i = idx >> 6, k = idx & 63;
        sG2T[k * 64 + i] = gw2[idx];
        sG3T[k * 64 + i] = gw3[idx];
    }
    if (tid < 64) { sB1[tid] = gb1[tid]; sB2[tid] = gb2[tid]; sB3[tid] = gb3[tid]; }

    int e = blockIdx.x * 256 + tid;
    bool valid = e < NE;
    int ee = valid ? e : 0;
    int src = esrc[ee], dst = edst[ee];

    float s0 = shifts[ee * 3 + 0], s1 = shifts[ee * 3 + 1], s2 = shifts[ee * 3 + 2];
    const float* cb = cell + batch[src] * 9;
    float vx = pos[dst * 3 + 0] - pos[src * 3 + 0] + s0 * cb[0] + s1 * cb[3] + s2 * cb[6];
    float vy = pos[dst * 3 + 1] - pos[src * 3 + 1] + s0 * cb[1] + s1 * cb[4] + s2 * cb[7];
    float vz = pos[dst * 3 + 2] - pos[src * 3 + 2] + s0 * cb[2] + s1 * cb[5] + s2 * cb[8];
    float r  = sqrtf(vx * vx + vy * vy + vz * vz + 1e-12f);
    float ir = __fdividef(1.0f, r);
    float ux = vx * ir, uy = vy * ir, uz = vz * ir;

    float sh[9];
    sh[0] = 1.0f;
    sh[1] = 1.7320508075688772f * ux;
    sh[2] = 1.7320508075688772f * uy;
    sh[3] = 1.7320508075688772f * uz;
    sh[4] = 3.872983346207417f * ux * uy;
    sh[5] = 3.872983346207417f * uy * uz;
    sh[6] = 1.118033988749895f * (2.0f * uz * uz - ux * ux - uy * uy);
    sh[7] = 3.872983346207417f * ux * uz;
    sh[8] = 1.9364916731037085f * (ux * ux - uy * uy);

    float xr = fminf(r * 0.2f, 1.0f);
    float mk = (r <= 5.0f) ? 2.8284271247461903f : 0.0f;
    float emb[8];
    #pragma unroll
    for (int j = 0; j < 8; j++) {
        float t = (xr - (float)j * (1.0f / 7.0f)) * 7.0f;
        emb[j] = __expf(-0.5f * t * t) * mk;
    }
    u64 embp[4];
    #pragma unroll
    for (int j = 0; j < 4; j++) embp[j] = fpack(emb[2 * j], emb[2 * j + 1]);

    float4 as0 = *(const float4*)(g_Ai + src * 8);
    float4 as1 = *(const float4*)(g_Ai + src * 8 + 4);
    float4 ad0 = *(const float4*)(g_Ai + dst * 8);
    float4 ad1 = *(const float4*)(g_Ai + dst * 8 + 4);
    sAs[0 * 256 + tid] = as0.x; sAs[1 * 256 + tid] = as0.y; sAs[2 * 256 + tid] = as0.z; sAs[3 * 256 + tid] = as0.w;
    sAs[4 * 256 + tid] = as1.x; sAs[5 * 256 + tid] = as1.y; sAs[6 * 256 + tid] = as1.z; sAs[7 * 256 + tid] = as1.w;
    sAd[0 * 256 + tid] = ad0.x; sAd[1 * 256 + tid] = ad0.y; sAd[2 * 256 + tid] = ad0.z; sAd[3 * 256 + tid] = ad0.w;
    sAd[4 * 256 + tid] = ad1.x; sAd[5 * 256 + tid] = ad1.y; sAd[6 * 256 + tid] = ad1.z; sAd[7 * 256 + tid] = ad1.w;

    __syncthreads();

    u64 h1[32];
    #pragma unroll
    for (int k = 0; k < 64; k += 2) {
        float o[2];
        #pragma unroll
        for (int kk = 0; kk < 2; kk++) {
            const u64* wr = (const u64*)(sG1T + (k + kk) * 8);
            ulonglong2 w01 = *(const ulonglong2*)(wr);
            ulonglong2 w23 = *(const ulonglong2*)(wr + 2);
            u64 a0 = f2mul(w01.x, embp[0]);
            u64 a1 = f2mul(w01.y, embp[1]);
            a0 = f2fma(w23.x, embp[2], a0);
            a1 = f2fma(w23.y, embp[3], a1);
            u64 s = f2add(a0, a1);
            float2 sv = funpack(s);
            o[kk] = silu_f(sv.x + sv.y + sB1[k + kk]);
        }
        h1[k >> 1] = fpack(o[0], o[1]);
    }
    u64 h2[32];
    layer64p(sG2T, sB2, h1, h2);
    u64 h3[32];
    layer64p(sG3T, sB3, h2, h3);

    u64 g[16];
    #pragma unroll
    for (int i = 0; i < 16; i++) g[i] = 0ull;

    #pragma unroll 1
    for (int ch = 0; ch < 8; ch++) {
        __syncthreads();
        int cbase = ch << 7;
        #pragma unroll
        for (int t2 = 0; t2 < 32; t2++) {
            int idx = t2 * 256 + tid;
            int k = idx >> 7, c = idx & 127;
            sChunk[c * 68 + k] = gw4[k * 1024 + cbase + c];
        }
        if (tid < 128) sBias[tid] = gb4[cbase + tid];
        __syncthreads();

        if (ch < 4)       chunk_accum_f<8, 0>(sChunk, sBias, sAs, sAd, tid, ch * 16, h3, g);
        else if (ch < 6)  chunk_accum_f<4, 8>(sChunk, sBias, sAs, sAd, tid, (ch - 4) * 32, h3, g);
        else              chunk_accum_f<4, 12>(sChunk, sBias, sAs, sAd, tid, (ch - 6) * 32, h3, g);
    }

    if (valid) {
        float gs[16];
        #pragma unroll
        for (int u = 0; u < 16; u++) {
            float2 gv = funpack(g[u]);
            gs[u] = gv.x + gv.y;
        }
        float* o = out + dst * 40;
        const float alpha = 0.125f;
        #pragma unroll
        for (int u = 0; u < 8; u++) atomicAdd(o + u, alpha * gs[u]);
        #pragma unroll
        for (int u = 0; u < 4; u++)
            #pragma unroll
            for (int m = 0; m < 3; m++)
                atomicAdd(o + 8 + u * 3 + m, alpha * gs[8 + u] * sh[1 + m]);
        #pragma unroll
        for (int u = 0; u < 4; u++)
            #pragma unroll
            for (int m = 0; m < 5; m++)
                atomicAdd(o + 20 + u * 5 + m, alpha * gs[12 + u] * sh[4 + m]);
        atomicAdd(&g_cnt[dst], 1.0f);
    }
#endif
}

// ---------------- normalize ----------------
__global__ void norm_kernel(float* __restrict__ out) {
    int i = blockIdx.x * 256 + threadIdx.x;
    if (i < NN * 40) {
        float c = g_cnt[i / 40];
        out[i] = out[i] / fmaxf(c, 1.0f);
    }
}

// ---------------- launch ----------------
extern "C" void kernel_launch(void* const* d_in, const int* in_sizes, int n_in,
                              void* d_out, int out_size)
{
    const float* pos        = (const float*)d_in[0];
    const float* shifts     = (const float*)d_in[1];
    const float* cell       = (const float*)d_in[2];
    const float* atom_table = (const float*)d_in[3];
    const float* fw1 = (const float*)d_in[4];  const float* fb1 = (const float*)d_in[5];
    const float* fw2 = (const float*)d_in[6];  const float* fb2 = (const float*)d_in[7];
    const float* fw3 = (const float*)d_in[8];  const float* fb3 = (const float*)d_in[9];
    const float* gw1 = (const float*)d_in[10]; const float* gb1 = (const float*)d_in[11];
    const float* gw2 = (const float*)d_in[12]; const float* gb2 = (const float*)d_in[13];
    const float* gw3 = (const float*)d_in[14]; const float* gb3 = (const float*)d_in[15];
    const float* gw4 = (const float*)d_in[16]; const float* gb4 = (const float*)d_in[17];
    const int* A     = (const int*)d_in[18];
    const int* batch = (const int*)d_in[19];
    const int* esrc  = (const int*)d_in[20];
    const int* edst  = (const int*)d_in[21];
    float* out = (float*)d_out;

    const int SMEM_T = 120 * 1024;   // 1 CTA/SM (TMEM 512 cols)
    const int SMEM_F = 87296;
    cudaFuncSetAttribute(edge_tensor,   cudaFuncAttributeMaxDynamicSharedMemorySize, SMEM_T);
    cudaFuncSetAttribute(edge_fallback, cudaFuncAttributeMaxDynamicSharedMemorySize, SMEM_F);

    zero_kernel<<<(NN * 40 + 255) / 256, 256>>>(out);
    prep_w2<<<(65536 + 1024 + 8192 + 255) / 256, 256>>>(gw4, gb4, gw2, gw3);
    atom_kernel<<<(NN + 255) / 256, 256>>>(atom_table, fw1, fb1, fw2, fb2, fw3, fb3, A);
    // exactly one of these does work (compile-time arch gate)
    edge_tensor<<<(NE + 255) / 256, 256, SMEM_T>>>(pos, shifts, cell,
                                                   gw1, gb1, gb2, gb3,
                                                   batch, esrc, edst, out);
    edge_fallback<<<(NE + 255) / 256, 256, SMEM_F>>>(pos, shifts, cell,
                                                     gw1, gb1, gw2, gb2, gw3, gb3, gw4, gb4,
                                                     batch, esrc, edst, out);
    norm_kernel<<<(NN * 40 + 255) / 256, 256>>>(out);
}

// round 16
// speedup vs baseline: 1.3002x; 1.3002x over previous
#include <cuda_runtime.h>
#include <cuda_fp16.h>
#include <cstdint>

#define NN 25000
#define NE 400000

#if defined(__CUDA_ARCH_FEAT_SM103_ALL) || defined(__CUDA_ARCH_FEAT_SM101_ALL) || defined(__CUDA_ARCH_FEAT_SM100_ALL)
#define HAS_TCGEN05 1
#else
#define HAS_TCGEN05 0
#endif

typedef unsigned long long u64;

// ---------------- scratch ----------------
__device__ __align__(16) float g_Ai[NN * 8];
__device__ float g_cnt[NN];
// fp16 prepped weights (SW128 blocked):
//   g_W2h: 8 chunks x 16KB (B[n][pk], n<128, pk<64) + bias 16KB (B[n][kk], kk<64, 8 real)
__device__ __align__(16) __half g_W2h[8 * 8192 + 8192];
//   g_W23h: gw2 (8KB) + gw3 (8KB): B[n][k], n,k<64
__device__ __align__(16) __half g_W23h[8192];

__device__ __forceinline__ float silu_f(float v) {
    return v * __fdividef(1.0f, 1.0f + __expf(-v));
}

// ---- packed f32x2 (fallback path) ----
__device__ __forceinline__ u64 f2fma(u64 a, u64 b, u64 c) {
    u64 d; asm("fma.rn.f32x2 %0,%1,%2,%3;" : "=l"(d) : "l"(a), "l"(b), "l"(c)); return d;
}
__device__ __forceinline__ u64 f2mul(u64 a, u64 b) {
    u64 d; asm("mul.rn.f32x2 %0,%1,%2;" : "=l"(d) : "l"(a), "l"(b)); return d;
}
__device__ __forceinline__ u64 f2add(u64 a, u64 b) {
    u64 d; asm("add.rn.f32x2 %0,%1,%2;" : "=l"(d) : "l"(a), "l"(b)); return d;
}
__device__ __forceinline__ u64 fpack(float lo, float hi) {
    u64 d; asm("mov.b64 %0,{%1,%2};" : "=l"(d) : "f"(lo), "f"(hi)); return d;
}
__device__ __forceinline__ float2 funpack(u64 v) {
    float lo, hi; asm("mov.b64 {%0,%1},%2;" : "=f"(lo), "=f"(hi) : "l"(v));
    return make_float2(lo, hi);
}

// ---- scalar 64->64 layer (fallback path only) ----
__device__ __forceinline__ void layer64p(const float* __restrict__ Wt,
                                         const float* __restrict__ Bv,
                                         const u64 (&in)[32], u64 (&outp)[32])
{
    #pragma unroll
    for (int k = 0; k < 64; k += 2) {
        float o[2];
        #pragma unroll
        for (int kk = 0; kk < 2; kk++) {
            const u64* wr = (const u64*)(Wt + (k + kk) * 64);
            ulonglong2 w01 = *(const ulonglong2*)(wr);
            ulonglong2 w23 = *(const ulonglong2*)(wr + 2);
            u64 a0 = f2mul(w01.x, in[0]);
            u64 a1 = f2mul(w01.y, in[1]);
            u64 a2 = f2mul(w23.x, in[2]);
            u64 a3 = f2mul(w23.y, in[3]);
            #pragma unroll
            for (int i = 4; i < 32; i += 4) {
                ulonglong2 v01 = *(const ulonglong2*)(wr + i);
                ulonglong2 v23 = *(const ulonglong2*)(wr + i + 2);
                a0 = f2fma(v01.x, in[i + 0], a0);
                a1 = f2fma(v01.y, in[i + 1], a1);
                a2 = f2fma(v23.x, in[i + 2], a2);
                a3 = f2fma(v23.y, in[i + 3], a3);
            }
            u64 s = f2add(f2add(a0, a1), f2add(a2, a3));
            float2 sv = funpack(s);
            o[kk] = silu_f(sv.x + sv.y + Bv[k + kk]);
        }
        outp[k >> 1] = fpack(o[0], o[1]);
    }
}

#if HAS_TCGEN05
// ---------------- tcgen05 plumbing ----------------
__device__ __forceinline__ uint32_t smem_u32(const void* p) {
    uint32_t a;
    asm("{ .reg .u64 t; cvta.to.shared.u64 t, %1; cvt.u32.u64 %0, t; }" : "=r"(a) : "l"(p));
    return a;
}
__device__ __forceinline__ uint32_t elect1() {
    uint32_t p;
    asm volatile("{\n\t.reg .pred p;\n\telect.sync _|p, 0xFFFFFFFF;\n\tselp.b32 %0,1,0,p;\n\t}" : "=r"(p));
    return p;
}
__device__ __forceinline__ uint32_t h2pack(float lo, float hi) {
    __half2 h = __floats2half2_rn(lo, hi);
    return *reinterpret_cast<uint32_t*>(&h);
}

#define TCGEN05_ALLOC(saddr, ncols) \
    asm volatile("tcgen05.alloc.cta_group::1.sync.aligned.shared::cta.b32 [%0], %1;" \
                 :: "r"((uint32_t)(saddr)), "r"((uint32_t)(ncols)) : "memory")
#define TCGEN05_RELINQ() \
    asm volatile("tcgen05.relinquish_alloc_permit.cta_group::1.sync.aligned;")
#define TCGEN05_DEALLOC(tmem, ncols) \
    asm volatile("tcgen05.dealloc.cta_group::1.sync.aligned.b32 %0, %1;" :: "r"(tmem), "r"((uint32_t)(ncols)))
#define TCGEN05_COMMIT(mbar) \
    asm volatile("tcgen05.commit.cta_group::1.mbarrier::arrive::one.shared::cluster.b64 [%0];" \
                 :: "r"((uint32_t)(mbar)) : "memory")
#define TCGEN05_WAIT_ST()  asm volatile("tcgen05.wait::st.sync.aligned;" ::: "memory")
#define TCGEN05_WAIT_LD()  asm volatile("tcgen05.wait::ld.sync.aligned;" ::: "memory")
#define TCGEN05_FENCE_BEFORE() asm volatile("tcgen05.fence::before_thread_sync;" ::: "memory")
#define TCGEN05_FENCE_AFTER()  asm volatile("tcgen05.fence::after_thread_sync;" ::: "memory")
#define FENCE_PROXY() asm volatile("fence.proxy.async.shared::cta;" ::: "memory")
#define MBARRIER_INIT(mbar, cnt) \
    asm volatile("mbarrier.init.shared.b64 [%0], %1;" :: "r"((uint32_t)(mbar)), "r"((uint32_t)(cnt)) : "memory")
#define MBARRIER_EXPECT_TX(mbar, bytes) \
    asm volatile("mbarrier.arrive.expect_tx.shared.b64 _, [%0], %1;" \
                 :: "r"((uint32_t)(mbar)), "r"((uint32_t)(bytes)) : "memory")
#define BULK_G2S(dst, src, bytes, mbar) \
    asm volatile("cp.async.bulk.shared::cluster.global.mbarrier::complete_tx::bytes [%0], [%1], %2, [%3];" \
                 :: "r"((uint32_t)(dst)), "l"(src), "r"((uint32_t)(bytes)), "r"((uint32_t)(mbar)) : "memory")
#define MBARRIER_WAIT0(mbar_a) do { \
    uint32_t _m = (uint32_t)(mbar_a); uint32_t _d; \
    asm volatile("{\n\t.reg .pred p;\n\tmbarrier.try_wait.parity.acquire.cta.shared::cta.b64 p, [%1], 0;\n\tselp.b32 %0,1,0,p;\n\t}" \
        : "=r"(_d) : "r"(_m) : "memory"); \
    if (!_d) { \
        asm volatile("{\n\t.reg .pred P1;\n\tWL_%=:\n\tmbarrier.try_wait.parity.acquire.cta.shared::cta.b64 P1, [%0], 0, 0x989680;\n\t@P1 bra.uni WD_%=;\n\tbra.uni WL_%=;\n\tWD_%=:\n\t}" \
            :: "r"(_m) : "memory"); \
    } \
} while (0)

#define TCGEN05_LD_X32(r, addr) \
    asm volatile("tcgen05.ld.sync.aligned.32x32b.x32.b32 " \
        "{%0,%1,%2,%3,%4,%5,%6,%7,%8,%9,%10,%11,%12,%13,%14,%15," \
        "%16,%17,%18,%19,%20,%21,%22,%23,%24,%25,%26,%27,%28,%29,%30,%31}, [%32];" \
        : "=r"((r)[0]),"=r"((r)[1]),"=r"((r)[2]),"=r"((r)[3]),"=r"((r)[4]),"=r"((r)[5]),"=r"((r)[6]),"=r"((r)[7]), \
          "=r"((r)[8]),"=r"((r)[9]),"=r"((r)[10]),"=r"((r)[11]),"=r"((r)[12]),"=r"((r)[13]),"=r"((r)[14]),"=r"((r)[15]), \
          "=r"((r)[16]),"=r"((r)[17]),"=r"((r)[18]),"=r"((r)[19]),"=r"((r)[20]),"=r"((r)[21]),"=r"((r)[22]),"=r"((r)[23]), \
          "=r"((r)[24]),"=r"((r)[25]),"=r"((r)[26]),"=r"((r)[27]),"=r"((r)[28]),"=r"((r)[29]),"=r"((r)[30]),"=r"((r)[31]) \
        : "r"(addr))

#define TCGEN05_ST_X32(addr, r) \
    asm volatile("tcgen05.st.sync.aligned.32x32b.x32.b32 [%0], " \
        "{%1,%2,%3,%4,%5,%6,%7,%8,%9,%10,%11,%12,%13,%14,%15,%16," \
        "%17,%18,%19,%20,%21,%22,%23,%24,%25,%26,%27,%28,%29,%30,%31,%32};" \
        :: "r"(addr), \
           "r"((r)[0]),"r"((r)[1]),"r"((r)[2]),"r"((r)[3]),"r"((r)[4]),"r"((r)[5]),"r"((r)[6]),"r"((r)[7]), \
           "r"((r)[8]),"r"((r)[9]),"r"((r)[10]),"r"((r)[11]),"r"((r)[12]),"r"((r)[13]),"r"((r)[14]),"r"((r)[15]), \
           "r"((r)[16]),"r"((r)[17]),"r"((r)[18]),"r"((r)[19]),"r"((r)[20]),"r"((r)[21]),"r"((r)[22]),"r"((r)[23]), \
           "r"((r)[24]),"r"((r)[25]),"r"((r)[26]),"r"((r)[27]),"r"((r)[28]),"r"((r)[29]),"r"((r)[30]),"r"((r)[31]) \
        : "memory")

#define TCGEN05_ST_X16(addr, r) \
    asm volatile("tcgen05.st.sync.aligned.32x32b.x16.b32 [%0], " \
        "{%1,%2,%3,%4,%5,%6,%7,%8,%9,%10,%11,%12,%13,%14,%15,%16};" \
        :: "r"(addr), \
           "r"((r)[0]),"r"((r)[1]),"r"((r)[2]),"r"((r)[3]),"r"((r)[4]),"r"((r)[5]),"r"((r)[6]),"r"((r)[7]), \
           "r"((r)[8]),"r"((r)[9]),"r"((r)[10]),"r"((r)[11]),"r"((r)[12]),"r"((r)[13]),"r"((r)[14]),"r"((r)[15]) \
        : "memory")

// idesc f16 (atype=btype=F16=0): dtype F32 bit4; N>>3 <<17; M>>4 <<24
static constexpr uint32_t IDESC_N64F  = (1u << 4) | (8u << 17)  | (8u << 24);
static constexpr uint32_t IDESC_N128F = (1u << 4) | (16u << 17) | (8u << 24);
static constexpr uint64_t DESC_BASE =
    (uint64_t(2) << 61) | (uint64_t(1) << 46) | (uint64_t(64) << 32) | (uint64_t(1) << 16);
__device__ __forceinline__ uint64_t mkdesc(uint32_t saddr) {
    return DESC_BASE | ((uint64_t)(saddr >> 4) & 0x3FFF);
}
__device__ __forceinline__ void mma_f16(uint32_t d, uint32_t a, uint64_t bd, uint32_t idesc, bool acc) {
    uint32_t en = acc ? 1u : 0u;
    asm volatile(
        "{\n\t.reg .pred p;\n\tsetp.ne.u32 p, %4, 0;\n\t"
        "tcgen05.mma.cta_group::1.kind::f16 [%0], [%1], %2, %3, {%5,%5,%5,%5}, p;\n\t}"
        :: "r"(d), "r"(a), "l"(bd), "r"(idesc), "r"(en), "r"(0u) : "memory");
}
__device__ __forceinline__ int w2_scol(int i, int n) {
    return (n < 64) ? (i * 64 + n)
         : (n < 96) ? (512 + i * 32 + (n - 64))
                    : (768 + i * 32 + (n - 96));
}
#endif // HAS_TCGEN05

// ---------------- fallback L4 helper ----------------
template<int MUL, int GB>
__device__ __forceinline__ void chunk_accum_f(const float* __restrict__ sChunk,
                                              const float* __restrict__ sBias,
                                              const float* __restrict__ sAs,
                                              const float* __restrict__ sAd,
                                              int tid, int pair_base,
                                              const u64 (&h3)[32], u64 (&g)[16])
{
    const int NP = 128 / MUL;
    #pragma unroll 1
    for (int p = 0; p < NP; p++) {
        int ij = pair_base + p;
        float pij = sAs[(ij >> 3) * 256 + tid] * sAd[(ij & 7) * 256 + tid];
        u64 pijp = fpack(pij, pij);
        const float* colb = sChunk + p * MUL * 68;
        #pragma unroll
        for (int u = 0; u < MUL; u++) {
            const u64* col = (const u64*)(colb + u * 68);
            ulonglong2 w01 = *(const ulonglong2*)(col);
            ulonglong2 w23 = *(const ulonglong2*)(col + 2);
            u64 a0 = f2fma(w01.x, h3[0], fpack(sBias[p * MUL + u], 0.0f));
            u64 a1 = f2mul(w01.y, h3[1]);
            u64 a2 = f2mul(w23.x, h3[2]);
            u64 a3 = f2mul(w23.y, h3[3]);
            #pragma unroll
            for (int i = 4; i < 32; i += 4) {
                ulonglong2 v01 = *(const ulonglong2*)(col + i);
                ulonglong2 v23 = *(const ulonglong2*)(col + i + 2);
                a0 = f2fma(v01.x, h3[i + 0], a0);
                a1 = f2fma(v01.y, h3[i + 1], a1);
                a2 = f2fma(v23.x, h3[i + 2], a2);
                a3 = f2fma(v23.y, h3[i + 3], a3);
            }
            u64 s = f2add(f2add(a0, a1), f2add(a2, a3));
            g[GB + u] = f2fma(pijp, s, g[GB + u]);
        }
    }
}

// ---------------- zero ----------------
__global__ void zero_kernel(float* __restrict__ out) {
    int i = blockIdx.x * 256 + threadIdx.x;
    if (i < NN * 40) out[i] = 0.0f;
    if (i < NN) g_cnt[i] = 0.0f;
}

// ---------------- prep: weights -> fp16 SW128 blocked ----------------
__global__ void prep_w2(const float* __restrict__ gw4, const float* __restrict__ gb4,
                        const float* __restrict__ gw2, const float* __restrict__ gw3) {
#if HAS_TCGEN05
    int idx = blockIdx.x * 256 + threadIdx.x;
    char* W2b = (char*)g_W2h;
    char* W23b = (char*)g_W23h;
    if (idx < 65536) {
        // chunks: c, pk<64, n<128 ; p = 64c+pk -> k=p>>3, i=p&7
        int c = idx >> 13, r = idx & 8191;
        int pk = r >> 7, n = r & 127;
        int p = c * 64 + pk;
        int k = p >> 3, i = p & 7;
        uint32_t off = (uint32_t)((n >> 3) * 1024 + (n & 7) * 128 + pk * 2);
        off ^= (off >> 3) & 0x70;
        *(__half*)(W2b + c * 16384 + off) = __float2half_rn(gw4[k * 1024 + w2_scol(i, n)]);
    } else if (idx < 65536 + 8192) {
        // bias: kk<64 (8 real), n<128
        int r = idx - 65536;
        int kk = r >> 7, n = r & 127;
        float v = (kk < 8) ? gb4[w2_scol(kk, n)] : 0.0f;
        uint32_t off = (uint32_t)((n >> 3) * 1024 + (n & 7) * 128 + kk * 2);
        off ^= (off >> 3) & 0x70;
        *(__half*)(W2b + 8 * 16384 + off) = __float2half_rn(v);
    } else if (idx < 65536 + 8192 + 8192) {
        // W23: layer l, k<64, n<64
        int r = idx - 73728;
        int layer = r >> 12, rr = r & 4095;
        int k = rr >> 6, n = rr & 63;
        const float* W = layer ? gw3 : gw2;
        uint32_t off = (uint32_t)((n >> 3) * 1024 + (n & 7) * 128 + k * 2);
        off ^= (off >> 3) & 0x70;
        *(__half*)(W23b + layer * 8192 + off) = __float2half_rn(W[k * 64 + n]);
    }
#endif
}

// ---------------- atom MLP 16->64->32->8 ----------------
__global__ void atom_kernel(const float* __restrict__ atom_table,
                            const float* __restrict__ fw1, const float* __restrict__ fb1,
                            const float* __restrict__ fw2, const float* __restrict__ fb2,
                            const float* __restrict__ fw3, const float* __restrict__ fb3,
                            const int* __restrict__ A)
{
    __shared__ float s[1024 + 64 + 2048 + 32 + 256 + 8];
    float* sW1 = s;             float* sB1 = sW1 + 1024;
    float* sW2 = sB1 + 64;      float* sB2 = sW2 + 2048;
    float* sW3 = sB2 + 32;      float* sB3 = sW3 + 256;
    int tid = threadIdx.x;
    for (int i = tid; i < 1024; i += 256) sW1[i] = fw1[i];
    for (int i = tid; i < 2048; i += 256) sW2[i] = fw2[i];
    for (int i = tid; i < 256; i += 256) sW3[i] = fw3[i];
    if (tid < 64) sB1[tid] = fb1[tid];
    if (tid < 32) sB2[tid] = fb2[tid];
    if (tid < 8)  sB3[tid] = fb3[tid];
    __syncthreads();

    int n = blockIdx.x * 256 + tid;
    if (n >= NN) return;
    float e[16];
    const float* at = atom_table + A[n] * 16;
    #pragma unroll
    for (int i = 0; i < 16; i++) e[i] = at[i];
    float h1[64];
    #pragma unroll
    for (int k = 0; k < 64; k++) {
        float a = sB1[k];
        #pragma unroll
        for (int i = 0; i < 16; i++) a = fmaf(e[i], sW1[i * 64 + k], a);
        h1[k] = silu_f(a);
    }
    float h2[32];
    #pragma unroll
    for (int k = 0; k < 32; k++) {
        float a = sB2[k];
        #pragma unroll
        for (int i = 0; i < 64; i++) a = fmaf(h1[i], sW2[i * 32 + k], a);
        h2[k] = silu_f(a);
    }
    #pragma unroll
    for (int k = 0; k < 8; k++) {
        float a = sB3[k];
        #pragma unroll
        for (int i = 0; i < 32; i++) a = fmaf(h2[i], sW3[i * 8 + k], a);
        g_Ai[n * 8 + k] = a;
    }
}

// ================================================================
// TENSOR kernel (fp16 MMA): 128 edges/CTA, 2 CTAs/SM, bias-seeded D,
// pipelined L4 over 2 A-halves (32 cols each). TMEM 256 cols.
// ================================================================
__global__ void __launch_bounds__(128, 2) edge_tensor(
    const float* __restrict__ pos, const float* __restrict__ shifts,
    const float* __restrict__ cell,
    const float* __restrict__ gw1, const float* __restrict__ gb1,
    const float* __restrict__ gb2, const float* __restrict__ gb3,
    const int* __restrict__ batch,
    const int* __restrict__ esrc, const int* __restrict__ edst,
    float* __restrict__ out)
{
#if HAS_TCGEN05
    extern __shared__ float smraw[];
    char* ab = (char*)(((uintptr_t)(char*)smraw + 1023) & ~(uintptr_t)1023);
    float* smf  = (float*)ab;
    // bytes: W23h [0,16K) biasb [16K,32K) buf0 [32K,48K) buf1 [48K,64K) sH3h [64K,80K)
    __half* sH3h = (__half*)(smf + 16384);   // [k][tid], 64x128 fp16
    float* sG1T = smf + 20480;   // 512
    float* sB1  = smf + 20992;   // 64
    float* sB2  = smf + 21056;   // 64
    float* sB3  = smf + 21120;   // 64
    volatile uint32_t* sTm = (volatile uint32_t*)(smf + 21184);
    uint32_t mbar0 = smem_u32((const void*)(smf + 21186));  // 21 x 8B
    #define MBAR(i) (mbar0 + 8u * (uint32_t)(i))
    // 0..7 copy chunk c; 8 copy bias; 9..16 mma chunk c; 17 mma bias; 18 mma L2; 19 mma L3; 20 copy W23

    int tid = threadIdx.x;
    int wid = tid >> 5;
    uint32_t woff = (uint32_t)wid << 21;
    uint32_t smem_base32 = smem_u32(ab);

    if (wid == 0) {
        TCGEN05_ALLOC(smem_u32((const void*)sTm), 256);
        TCGEN05_RELINQ();
    }
    if (tid == 0) {
        #pragma unroll
        for (int i = 0; i < 21; i++) MBARRIER_INIT(MBAR(i), 1);
        // prologue: W23 (16K), bias (16K), chunk0 -> buf0, chunk1 -> buf1
        MBARRIER_EXPECT_TX(MBAR(20), 16384);
        BULK_G2S(smem_base32, (const void*)(g_W23h), 16384, MBAR(20));
        MBARRIER_EXPECT_TX(MBAR(8), 16384);
        BULK_G2S(smem_base32 + 16384u, (const void*)((const char*)g_W2h + 8 * 16384), 16384, MBAR(8));
        MBARRIER_EXPECT_TX(MBAR(0), 16384);
        BULK_G2S(smem_base32 + 32768u, (const void*)(g_W2h), 16384, MBAR(0));
        MBARRIER_EXPECT_TX(MBAR(1), 16384);
        BULK_G2S(smem_base32 + 49152u, (const void*)((const char*)g_W2h + 16384), 16384, MBAR(1));
    }

    // stage small scalar weights
    for (int i = tid; i < 512; i += 128) { int ii = i >> 6, k = i & 63; sG1T[k * 8 + ii] = gw1[i]; }
    if (tid < 64) { sB1[tid] = gb1[tid]; sB2[tid] = gb2[tid]; sB3[tid] = gb3[tid]; }

    // ---- per-edge geometry (400000 = 3125*128) ----
    int e = blockIdx.x * 128 + tid;
    int src = esrc[e], dst = edst[e];

    float s0 = shifts[e * 3 + 0], s1 = shifts[e * 3 + 1], s2 = shifts[e * 3 + 2];
    const float* cb = cell + batch[src] * 9;
    float vx = pos[dst * 3 + 0] - pos[src * 3 + 0] + s0 * cb[0] + s1 * cb[3] + s2 * cb[6];
    float vy = pos[dst * 3 + 1] - pos[src * 3 + 1] + s0 * cb[1] + s1 * cb[4] + s2 * cb[7];
    float vz = pos[dst * 3 + 2] - pos[src * 3 + 2] + s0 * cb[2] + s1 * cb[5] + s2 * cb[8];
    float r  = sqrtf(vx * vx + vy * vy + vz * vz + 1e-12f);
    float ir = __fdividef(1.0f, r);
    float ux = vx * ir, uy = vy * ir, uz = vz * ir;

    float sh[9];
    sh[0] = 1.0f;
    sh[1] = 1.7320508075688772f * ux;
    sh[2] = 1.7320508075688772f * uy;
    sh[3] = 1.7320508075688772f * uz;
    sh[4] = 3.872983346207417f * ux * uy;
    sh[5] = 3.872983346207417f * uy * uz;
    sh[6] = 1.118033988749895f * (2.0f * uz * uz - ux * ux - uy * uy);
    sh[7] = 3.872983346207417f * ux * uz;
    sh[8] = 1.9364916731037085f * (ux * ux - uy * uy);

    float xr = fminf(r * 0.2f, 1.0f);
    float mk = (r <= 5.0f) ? 2.8284271247461903f : 0.0f;
    float emb[8];
    #pragma unroll
    for (int j = 0; j < 8; j++) {
        float t = (xr - (float)j * (1.0f / 7.0f)) * 7.0f;
        emb[j] = __expf(-0.5f * t * t) * mk;
    }

    float As[8], Ad[8];
    {
        float4 a0 = *(const float4*)(g_Ai + src * 8);
        float4 a1 = *(const float4*)(g_Ai + src * 8 + 4);
        float4 b0 = *(const float4*)(g_Ai + dst * 8);
        float4 b1 = *(const float4*)(g_Ai + dst * 8 + 4);
        As[0]=a0.x; As[1]=a0.y; As[2]=a0.z; As[3]=a0.w; As[4]=a1.x; As[5]=a1.y; As[6]=a1.z; As[7]=a1.w;
        Ad[0]=b0.x; Ad[1]=b0.y; Ad[2]=b0.z; Ad[3]=b0.w; Ad[4]=b1.x; Ad[5]=b1.y; Ad[6]=b1.z; Ad[7]=b1.w;
    }

    __syncthreads();        // alloc + staging visible
    uint32_t tb = *sTm;     // TMEM: A fp16 cols 0..63 (two 32-col halves), D fp32 cols 128..255

    // ---- L1 scalar (8->64) -> STTM A[0..31] (fp16 pairs) ----
    {
        uint32_t rr[32];
        #pragma unroll
        for (int j = 0; j < 32; j++) {
            float v[2];
            #pragma unroll
            for (int kk = 0; kk < 2; kk++) {
                int k = 2 * j + kk;
                float a = sB1[k];
                #pragma unroll
                for (int i = 0; i < 8; i++) a = fmaf(emb[i], sG1T[k * 8 + i], a);
                v[kk] = silu_f(a);
            }
            rr[j] = h2pack(v[0], v[1]);
        }
        TCGEN05_ST_X32(tb + woff, rr);
    }
    TCGEN05_WAIT_ST();
    TCGEN05_FENCE_BEFORE();
    __syncthreads();

    // ---- L2 MMA: D[128..191] = h1 @ gw2 (W23h lo), K=64 = 4 steps ----
    if (wid == 0) {
        TCGEN05_FENCE_AFTER();
        MBARRIER_WAIT0(MBAR(20));
        if (elect1()) {
            uint64_t bd = mkdesc(smem_base32);
            #pragma unroll
            for (int s = 0; s < 4; s++)
                mma_f16(tb + 128u, tb + s * 8, bd + 2 * s, IDESC_N64F, s > 0);
            TCGEN05_COMMIT(MBAR(18));
        }
    }
    MBARRIER_WAIT0(MBAR(18));
    TCGEN05_FENCE_AFTER();

    // act L2: h2 = silu(D + gb2) -> A[32..63] (fp16 pairs)
    #pragma unroll
    for (int b = 0; b < 2; b++) {
        uint32_t rr[32];
        TCGEN05_LD_X32(rr, tb + 128u + b * 32 + woff);
        TCGEN05_WAIT_LD();
        uint32_t pk[16];
        #pragma unroll
        for (int j = 0; j < 16; j++) {
            float v0 = silu_f(__uint_as_float(rr[2 * j])     + sB2[b * 32 + 2 * j]);
            float v1 = silu_f(__uint_as_float(rr[2 * j + 1]) + sB2[b * 32 + 2 * j + 1]);
            pk[j] = h2pack(v0, v1);
        }
        TCGEN05_ST_X16(tb + 32u + (uint32_t)b * 16u + woff, pk);
    }
    TCGEN05_WAIT_ST();
    TCGEN05_FENCE_BEFORE();
    __syncthreads();

    // ---- L3 MMA: D[128..191] = h2 @ gw3 (W23h hi) ----
    if (wid == 0) {
        TCGEN05_FENCE_AFTER();
        if (elect1()) {
            uint64_t bd = mkdesc(smem_base32 + 8192u);
            #pragma unroll
            for (int s = 0; s < 4; s++)
                mma_f16(tb + 128u, tb + 32u + s * 8, bd + 2 * s, IDESC_N64F, s > 0);
            TCGEN05_COMMIT(MBAR(19));
        }
    }
    MBARRIER_WAIT0(MBAR(19));
    TCGEN05_FENCE_AFTER();

    // act L3: h3 = silu(D + gb3) -> sH3h (fp16)
    #pragma unroll
    for (int b = 0; b < 2; b++) {
        uint32_t rr[32];
        TCGEN05_LD_X32(rr, tb + 128u + b * 32 + woff);
        TCGEN05_WAIT_LD();
        #pragma unroll
        for (int i = 0; i < 32; i++)
            sH3h[(b * 32 + i) * 128 + tid] = __float2half_rn(silu_f(__uint_as_float(rr[i]) + sB3[b * 32 + i]));
    }

    // ---- bias MMA seeds D (acc=false): K=16 (8 real As + 8 zero) ----
    {
        uint32_t rr[32];
        #pragma unroll
        for (int c = 0; c < 32; c++)
            rr[c] = (c < 4) ? h2pack(As[2 * c], As[2 * c + 1]) : 0u;
        TCGEN05_ST_X32(tb + woff, rr);   // A cols 0..31 (MMA reads 0..7)
        TCGEN05_WAIT_ST();
        TCGEN05_FENCE_BEFORE();
        __syncthreads();
        if (wid == 0) {
            TCGEN05_FENCE_AFTER();
            MBARRIER_WAIT0(MBAR(8));
            if (elect1()) {
                uint64_t bd = mkdesc(smem_base32 + 16384u);
                mma_f16(tb + 128u, tb, bd, IDESC_N128F, false);
                TCGEN05_COMMIT(MBAR(17));
            }
        }
        MBARRIER_WAIT0(MBAR(17));
        TCGEN05_FENCE_AFTER();
    }

    // ---- L4: 8 pipelined parts (K=64 each, 4 steps); A-half ping-pong (32 cols); D accumulates ----
    // chunk c buffer: even -> buf0 (32K), odd -> buf1 (48K)
    #pragma unroll 1
    for (int c = 0; c < 8; c++) {
        if (c >= 2) {
            MBARRIER_WAIT0(MBAR(9 + c - 2));      // frees A-half(c&1) and chunk-c's buffer
            TCGEN05_FENCE_AFTER();
            if (tid == 0) {
                MBARRIER_EXPECT_TX(MBAR(c), 16384);
                BULK_G2S(smem_base32 + ((c & 1) ? 49152u : 32768u),
                         (const void*)((const char*)g_W2h + c * 16384), 16384, MBAR(c));
            }
        }
        uint32_t abase = tb + (uint32_t)(c & 1) * 32u;
        {
            uint32_t rr[32];
            #pragma unroll
            for (int j = 0; j < 32; j++) {
                int q0 = 2 * j;
                float h3k = __half2float(sH3h[(8 * c + (q0 >> 3)) * 128 + tid]);
                rr[j] = h2pack(h3k * As[q0 & 7], h3k * As[(q0 + 1) & 7]);
            }
            TCGEN05_ST_X32(abase + woff, rr);
        }
        TCGEN05_WAIT_ST();
        TCGEN05_FENCE_BEFORE();
        __syncthreads();

        if (wid == 0) {
            TCGEN05_FENCE_AFTER();
            MBARRIER_WAIT0(MBAR(c));              // DMA complete
            if (elect1()) {
                uint64_t bd = mkdesc(smem_base32 + ((c & 1) ? 49152u : 32768u));
                #pragma unroll
                for (int s = 0; s < 4; s++)
                    mma_f16(tb + 128u, abase + (uint32_t)s * 8u, bd + 2 * s, IDESC_N128F, true);
                TCGEN05_COMMIT(MBAR(9 + c));
            }
        }
    }

    // ---- final waits + single readback + fold ----
    MBARRIER_WAIT0(MBAR(9 + 6));
    MBARRIER_WAIT0(MBAR(9 + 7));
    TCGEN05_FENCE_AFTER();

    float g[16];
    #pragma unroll
    for (int i = 0; i < 16; i++) g[i] = 0.0f;
    #pragma unroll
    for (int q = 0; q < 4; q++) {
        uint32_t rr[32];
        TCGEN05_LD_X32(rr, tb + 128u + 32u * q + woff);
        TCGEN05_WAIT_LD();
        if (q < 2) {
            #pragma unroll
            for (int c = 0; c < 32; c++)
                g[c & 7] = fmaf(Ad[4 * q + (c >> 3)], __uint_as_float(rr[c]), g[c & 7]);
        } else if (q == 2) {
            #pragma unroll
            for (int c = 0; c < 32; c++)
                g[8 + (c & 3)] = fmaf(Ad[c >> 2], __uint_as_float(rr[c]), g[8 + (c & 3)]);
        } else {
            #pragma unroll
            for (int c = 0; c < 32; c++)
                g[12 + (c & 3)] = fmaf(Ad[c >> 2], __uint_as_float(rr[c]), g[12 + (c & 3)]);
        }
    }

    // ---- scatter ----
    {
        float* o = out + dst * 40;
        const float alpha = 0.125f;
        #pragma unroll
        for (int u = 0; u < 8; u++) atomicAdd(o + u, alpha * g[u]);
        #pragma unroll
        for (int u = 0; u < 4; u++)
            #pragma unroll
            for (int m = 0; m < 3; m++)
                atomicAdd(o + 8 + u * 3 + m, alpha * g[8 + u] * sh[1 + m]);
        #pragma unroll
        for (int u = 0; u < 4; u++)
            #pragma unroll
            for (int m = 0; m < 5; m++)
                atomicAdd(o + 20 + u * 5 + m, alpha * g[12 + u] * sh[4 + m]);
        atomicAdd(&g_cnt[dst], 1.0f);
    }

    __syncthreads();
    if (wid == 0) TCGEN05_DEALLOC(tb, 256);
    #undef MBAR
#endif
}

// ================================================================
// FALLBACK kernel (R3 body). No-op on sm_103a builds.
// ================================================================
__global__ void __launch_bounds__(256) edge_fallback(
    const float* __restrict__ pos, const float* __restrict__ shifts,
    const float* __restrict__ cell,
    const float* __restrict__ gw1, const float* __restrict__ gb1,
    const float* __restrict__ gw2, const float* __restrict__ gb2,
    const float* __restrict__ gw3, const float* __restrict__ gb3,
    const float* __restrict__ gw4, const float* __restrict__ gb4,
    const int* __restrict__ batch,
    const int* __restrict__ esrc, const int* __restrict__ edst,
    float* __restrict__ out)
{
#if !HAS_TCGEN05
    extern __shared__ float sm[];
    float* sG1T  = sm;
    float* sB1   = sG1T + 512;
    float* sG2T  = sB1 + 64;
    float* sB2   = sG2T + 4096;
    float* sG3T  = sB2 + 64;
    float* sB3   = sG3T + 4096;
    float* sAs   = sB3 + 64;
    float* sAd   = sAs + 8 * 256;
    float* sBias = sAd + 8 * 256;
    float* sChunk = sBias + 128;

    int tid = threadIdx.x;
    for (int idx = tid; idx < 512; idx += 256) {
        int i = idx >> 6, k = idx & 63;
        sG1T[k * 8 + i] = gw1[idx];
    }
    for (int idx = tid; idx < 4096; idx += 256) {
        int i = idx >> 6, k = idx & 63;
        sG2T[k * 64 + i] = gw2[idx];
        sG3T[k * 64 + i] = gw3[idx];
    }
    if (tid < 64) { sB1[tid] = gb1[tid]; sB2[tid] = gb2[tid]; sB3[tid] = gb3[tid]; }

    int e = blockIdx.x * 256 + tid;
    bool valid = e < NE;
    int ee = valid ? e : 0;
    int src = esrc[ee], dst = edst[ee];

    float s0 = shifts[ee * 3 + 0], s1 = shifts[ee * 3 + 1], s2 = shifts[ee * 3 + 2];
    const float* cb = cell + batch[src] * 9;
    float vx = pos[dst * 3 + 0] - pos[src * 3 + 0] + s0 * cb[0] + s1 * cb[3] + s2 * cb[6];
    float vy = pos[dst * 3 + 1] - pos[src * 3 + 1] + s0 * cb[1] + s1 * cb[4] + s2 * cb[7];
    float vz = pos[dst * 3 + 2] - pos[src * 3 + 2] + s0 * cb[2] + s1 * cb[5] + s2 * cb[8];
    float r  = sqrtf(vx * vx + vy * vy + vz * vz + 1e-12f);
    float ir = __fdividef(1.0f, r);
    float ux = vx * ir, uy = vy * ir, uz = vz * ir;

    float sh[9];
    sh[0] = 1.0f;
    sh[1] = 1.7320508075688772f * ux;
    sh[2] = 1.7320508075688772f * uy;
    sh[3] = 1.7320508075688772f * uz;
    sh[4] = 3.872983346207417f * ux * uy;
    sh[5] = 3.872983346207417f * uy * uz;
    sh[6] = 1.118033988749895f * (2.0f * uz * uz - ux * ux - uy * uy);
    sh[7] = 3.872983346207417f * ux * uz;
    sh[8] = 1.9364916731037085f * (ux * ux - uy * uy);

    float xr = fminf(r * 0.2f, 1.0f);
    float mk = (r <= 5.0f) ? 2.8284271247461903f : 0.0f;
    float emb[8];
    #pragma unroll
    for (int j = 0; j < 8; j++) {
        float t = (xr - (float)j * (1.0f / 7.0f)) * 7.0f;
        emb[j] = __expf(-0.5f * t * t) * mk;
    }
    u64 embp[4];
    #pragma unroll
    for (int j = 0; j < 4; j++) embp[j] = fpack(emb[2 * j], emb[2 * j + 1]);

    float4 as0 = *(const float4*)(g_Ai + src * 8);
    float4 as1 = *(const float4*)(g_Ai + src * 8 + 4);
    float4 ad0 = *(const float4*)(g_Ai + dst * 8);
    float4 ad1 = *(const float4*)(g_Ai + dst * 8 + 4);
    sAs[0 * 256 + tid] = as0.x; sAs[1 * 256 + tid] = as0.y; sAs[2 * 256 + tid] = as0.z; sAs[3 * 256 + tid] = as0.w;
    sAs[4 * 256 + tid] = as1.x; sAs[5 * 256 + tid] = as1.y; sAs[6 * 256 + tid] = as1.z; sAs[7 * 256 + tid] = as1.w;
    sAd[0 * 256 + tid] = ad0.x; sAd[1 * 256 + tid] = ad0.y; sAd[2 * 256 + tid] = ad0.z; sAd[3 * 256 + tid] = ad0.w;
    sAd[4 * 256 + tid] = ad1.x; sAd[5 * 256 + tid] = ad1.y; sAd[6 * 256 + tid] = ad1.z; sAd[7 * 256 + tid] = ad1.w;

    __syncthreads();

    u64 h1[32];
    #pragma unroll
    for (int k = 0; k < 64; k += 2) {
        float o[2];
        #pragma unroll
        for (int kk = 0; kk < 2; kk++) {
            const u64* wr = (const u64*)(sG1T + (k + kk) * 8);
            ulonglong2 w01 = *(const ulonglong2*)(wr);
            ulonglong2 w23 = *(const ulonglong2*)(wr + 2);
            u64 a0 = f2mul(w01.x, embp[0]);
            u64 a1 = f2mul(w01.y, embp[1]);
            a0 = f2fma(w23.x, embp[2], a0);
            a1 = f2fma(w23.y, embp[3], a1);
            u64 s = f2add(a0, a1);
            float2 sv = funpack(s);
            o[kk] = silu_f(sv.x + sv.y + sB1[k + kk]);
        }
        h1[k >> 1] = fpack(o[0], o[1]);
    }
    u64 h2[32];
    layer64p(sG2T, sB2, h1, h2);
    u64 h3[32];
    layer64p(sG3T, sB3, h2, h3);

    u64 g[16];
    #pragma unroll
    for (int i = 0; i < 16; i++) g[i] = 0ull;

    #pragma unroll 1
    for (int ch = 0; ch < 8; ch++) {
        __syncthreads();
        int cbase = ch << 7;
        #pragma unroll
        for (int t2 = 0; t2 < 32; t2++) {
            int idx = t2 * 256 + tid;
            int k = idx >> 7, c = idx & 127;
            sChunk[c * 68 + k] = gw4[k * 1024 + cbase + c];
        }
        if (tid < 128) sBias[tid] = gb4[cbase + tid];
        __syncthreads();

        if (ch < 4)       chunk_accum_f<8, 0>(sChunk, sBias, sAs, sAd, tid, ch * 16, h3, g);
        else if (ch < 6)  chunk_accum_f<4, 8>(sChunk, sBias, sAs, sAd, tid, (ch - 4) * 32, h3, g);
        else              chunk_accum_f<4, 12>(sChunk, sBias, sAs, sAd, tid, (ch - 6) * 32, h3, g);
    }

    if (valid) {
        float gs[16];
        #pragma unroll
        for (int u = 0; u < 16; u++) {
            float2 gv = funpack(g[u]);
            gs[u] = gv.x + gv.y;
        }
        float* o = out + dst * 40;
        const float alpha = 0.125f;
        #pragma unroll
        for (int u = 0; u < 8; u++) atomicAdd(o + u, alpha * gs[u]);
        #pragma unroll
        for (int u = 0; u < 4; u++)
            #pragma unroll
            for (int m = 0; m < 3; m++)
                atomicAdd(o + 8 + u * 3 + m, alpha * gs[8 + u] * sh[1 + m]);
        #pragma unroll
        for (int u = 0; u < 4; u++)
            #pragma unroll
            for (int m = 0; m < 5; m++)
                atomicAdd(o + 20 + u * 5 + m, alpha * gs[12 + u] * sh[4 + m]);
        atomicAdd(&g_cnt[dst], 1.0f);
    }
#endif
}

// ---------------- normalize ----------------
__global__ void norm_kernel(float* __restrict__ out) {
    int i = blockIdx.x * 256 + threadIdx.x;
    if (i < NN * 40) {
        float c = g_cnt[i / 40];
        out[i] = out[i] / fmaxf(c, 1.0f);
    }
}

// ---------------- launch ----------------
extern "C" void kernel_launch(void* const* d_in, const int* in_sizes, int n_in,
                              void* d_out, int out_size)
{
    const float* pos        = (const float*)d_in[0];
    const float* shifts     = (const float*)d_in[1];
    const float* cell       = (const float*)d_in[2];
    const float* atom_table = (const float*)d_in[3];
    const float* fw1 = (const float*)d_in[4];  const float* fb1 = (const float*)d_in[5];
    const float* fw2 = (const float*)d_in[6];  const float* fb2 = (const float*)d_in[7];
    const float* fw3 = (const float*)d_in[8];  const float* fb3 = (const float*)d_in[9];
    const float* gw1 = (const float*)d_in[10]; const float* gb1 = (const float*)d_in[11];
    const float* gw2 = (const float*)d_in[12]; const float* gb2 = (const float*)d_in[13];
    const float* gw3 = (const float*)d_in[14]; const float* gb3 = (const float*)d_in[15];
    const float* gw4 = (const float*)d_in[16]; const float* gb4 = (const float*)d_in[17];
    const int* A     = (const int*)d_in[18];
    const int* batch = (const int*)d_in[19];
    const int* esrc  = (const int*)d_in[20];
    const int* edst  = (const int*)d_in[21];
    float* out = (float*)d_out;

    const int SMEM_T = 90112;    // ~88KB -> 2 CTAs/SM (TMEM 2x256 cols = 512)
    const int SMEM_F = 87296;
    cudaFuncSetAttribute(edge_tensor,   cudaFuncAttributeMaxDynamicSharedMemorySize, SMEM_T);
    cudaFuncSetAttribute(edge_fallback, cudaFuncAttributeMaxDynamicSharedMemorySize, SMEM_F);

    zero_kernel<<<(NN * 40 + 255) / 256, 256>>>(out);
    prep_w2<<<(65536 + 8192 + 8192 + 255) / 256, 256>>>(gw4, gb4, gw2, gw3);
    atom_kernel<<<(NN + 255) / 256, 256>>>(atom_table, fw1, fb1, fw2, fb2, fw3, fb3, A);
    // exactly one of these does work (compile-time arch gate)
    edge_tensor<<<NE / 128, 128, SMEM_T>>>(pos, shifts, cell,
                                           gw1, gb1, gb2, gb3,
                                           batch, esrc, edst, out);
    edge_fallback<<<(NE + 255) / 256, 256, SMEM_F>>>(pos, shifts, cell,
                                                     gw1, gb1, gw2, gb2, gw3, gb3, gw4, gb4,
                                                     batch, esrc, edst, out);
    norm_kernel<<<(NN * 40 + 255) / 256, 256>>>(out);
}